// round 12
// baseline (speedup 1.0000x reference)
#include <cuda_runtime.h>
#include <math.h>
#include <stdint.h>

// Problem constants
#define BB 256   // batch
#define TT 512   // time steps
#define DD 64    // input dim (layer 0)
#define HH 256   // hidden dim
#define G4H 1024 // 4*H

#define NBLK 128     // persistent grid (16 clusters x 8 CTAs), 1 block/SM
#define RTHREADS 128 // threads per persistent block (R8 proven tiling)
#define CLSZ 8       // cluster size = one batch group

typedef unsigned long long ull;

// ---------------- scratch (__device__ globals; no allocations allowed) ----------
__device__ float g_xproj[(size_t)TT * BB * G4H]; // 512 MB: x @ W_ih^T + bias, [T][B][4H]
__device__ float g_h0T[(size_t)TT * HH * BB];    // 128 MB: layer-0 outputs TRANSPOSED [T][H][B]
__device__ float g_hlast[HH * BB];               // final h of a layer, [H][B]

// ---------------- packed fp32x2 helpers (Blackwell FFMA2 via PTX) ---------------
__device__ __forceinline__ ull pack2(float lo, float hi) {
    ull r;
    asm("mov.b64 %0, {%1, %2};" : "=l"(r) : "f"(lo), "f"(hi));
    return r;
}
__device__ __forceinline__ void unpack2(ull v, float& lo, float& hi) {
    asm("mov.b64 {%0, %1}, %2;" : "=f"(lo), "=f"(hi) : "l"(v));
}
__device__ __forceinline__ void fma2(ull& d, ull a, ull b) {
    asm("fma.rn.f32x2 %0, %1, %2, %0;" : "+l"(d) : "l"(a), "l"(b));
}

// ---------------- fast activations (MUFU-based, ~1e-6 rel err) ------------------
__device__ __forceinline__ float sigf(float x) {
    return __fdividef(1.0f, 1.0f + __expf(-x));
}
__device__ __forceinline__ float tanf_fast(float x) {
    return __fdividef(2.0f, 1.0f + __expf(-2.0f * x)) - 1.0f;
}

// ---------------- DSMEM / mbarrier primitives ------------------------------------
__device__ __forceinline__ uint32_t smem_u32(const void* p) {
    uint32_t a;
    asm("{ .reg .u64 t; cvta.to.shared.u64 t, %1; cvt.u32.u64 %0, t; }"
        : "=r"(a) : "l"(p));
    return a;
}
__device__ __forceinline__ void mbar_init(uint32_t addr, uint32_t cnt) {
    asm volatile("mbarrier.init.shared.b64 [%0], %1;" :: "r"(addr), "r"(cnt) : "memory");
}
__device__ __forceinline__ void mbar_wait(uint32_t addr, uint32_t parity) {
    asm volatile(
        "{\n\t"
        ".reg .pred P;\n\t"
        "WL%=:\n\t"
        "mbarrier.try_wait.parity.acquire.cluster.shared::cta.b64 P, [%0], %1, 0x989680;\n\t"
        "@P bra WD%=;\n\t"
        "bra WL%=;\n\t"
        "WD%=:\n\t"
        "}" :: "r"(addr), "r"(parity) : "memory");
}
__device__ __forceinline__ uint32_t mapa_u32(uint32_t addr, uint32_t rank) {
    uint32_t r;
    asm("mapa.shared::cluster.u32 %0, %1, %2;" : "=r"(r) : "r"(addr), "r"(rank));
    return r;
}
__device__ __forceinline__ void send_slice(uint32_t rem_dst, uint32_t src,
                                           uint32_t rem_bar, uint32_t bytes) {
    asm volatile(
        "mbarrier.arrive.expect_tx.release.cluster.shared::cluster.b64 _, [%0], %1;"
        :: "r"(rem_bar), "r"(bytes) : "memory");
    asm volatile(
        "cp.async.bulk.shared::cluster.shared::cta.mbarrier::complete_tx::bytes "
        "[%0], [%1], %2, [%3];"
        :: "r"(rem_dst), "r"(src), "r"(bytes), "r"(rem_bar) : "memory");
}
__device__ __forceinline__ void cluster_barrier() {
    asm volatile("barrier.cluster.arrive.aligned;" ::: "memory");
    asm volatile("barrier.cluster.wait.aligned;" ::: "memory");
}

// ================================================================================
// Input-projection GEMM (unchanged, best-measured R9 version):
// out[m][gc] = sum_k A[m][k] * W[gc][k] + b_ih[gc] + b_hh[gc], m = t*BB + b.
// AMODE 0: A = x [B][T][D].  AMODE 1: A = g_h0T [T][H][B] (transposed).
// ================================================================================
template<int K, int AMODE>
__global__ __launch_bounds__(256)
void xproj_gemm(const float* __restrict__ A,
                const float* __restrict__ W,
                const float* __restrict__ bih,
                const float* __restrict__ bhh,
                float* __restrict__ out)
{
    __shared__ float At[32 * 68];    // [k][row], padded
    __shared__ float Wt[32 * 130];   // [k][col], even pad (8B-aligned rows)

    const int tid = threadIdx.x;
    const int tx  = tid & 15;        // col-pair lane: cols 2tx + 32j
    const int ty  = tid >> 4;        // rows ty + 16r
    const int m0  = blockIdx.x * 64;
    const int n0  = blockIdx.y * 128;

    ull acc[4][4];
#pragma unroll
    for (int r = 0; r < 4; r++)
#pragma unroll
        for (int j = 0; j < 4; j++) acc[r][j] = 0ull;

    for (int ks = 0; ks < K; ks += 32) {
        if (AMODE == 0) {
#pragma unroll
            for (int q = 0; q < 2; q++) {
                int chunk = tid + 256 * q;          // 512 float4 chunks
                int row   = chunk >> 3;
                int kq    = (chunk & 7) << 2;
                int m     = m0 + row;
                const float* ap = A + (size_t)(m & 255) * (TT * DD)
                                    + (size_t)(m >> 8) * DD + ks + kq;
                float4 v = *reinterpret_cast<const float4*>(ap);
                At[(kq + 0) * 68 + row] = v.x;
                At[(kq + 1) * 68 + row] = v.y;
                At[(kq + 2) * 68 + row] = v.z;
                At[(kq + 3) * 68 + row] = v.w;
            }
        } else {
            int t  = m0 >> 8;
            int b0 = m0 & 255;
#pragma unroll
            for (int q = 0; q < 2; q++) {
                int chunk = tid + 256 * q;          // 512 float4 chunks
                int k  = chunk >> 4;                // 0..31
                int b4 = (chunk & 15) << 2;
                float4 v = *reinterpret_cast<const float4*>(
                    A + ((size_t)t * HH + ks + k) * BB + b0 + b4);
                *reinterpret_cast<float4*>(&At[k * 68 + b4]) = v;
            }
        }
#pragma unroll
        for (int q = 0; q < 4; q++) {
            int chunk = tid + 256 * q;              // 1024 float4 chunks
            int col   = chunk >> 3;
            int kq    = (chunk & 7) << 2;
            float4 v  = *reinterpret_cast<const float4*>(
                W + (size_t)(n0 + col) * K + ks + kq);
            Wt[(kq + 0) * 130 + col] = v.x;
            Wt[(kq + 1) * 130 + col] = v.y;
            Wt[(kq + 2) * 130 + col] = v.z;
            Wt[(kq + 3) * 130 + col] = v.w;
        }
        __syncthreads();

#pragma unroll 8
        for (int k = 0; k < 32; k++) {
            ull w[4];
#pragma unroll
            for (int j = 0; j < 4; j++)
                w[j] = *reinterpret_cast<const ull*>(
                    &Wt[k * 130 + 2 * tx + 32 * j]);
#pragma unroll
            for (int r = 0; r < 4; r++) {
                float a = At[k * 68 + ty + 16 * r];
                ull aa = pack2(a, a);
#pragma unroll
                for (int j = 0; j < 4; j++) fma2(acc[r][j], aa, w[j]);
            }
        }
        __syncthreads();
    }

#pragma unroll
    for (int r = 0; r < 4; r++) {
        int m = m0 + ty + 16 * r;
#pragma unroll
        for (int j = 0; j < 4; j++) {
            int gc = n0 + 2 * tx + 32 * j;
            float lo, hi;
            unpack2(acc[r][j], lo, hi);
            float2 o;
            o.x = lo + bih[gc]     + bhh[gc];
            o.y = hi + bih[gc + 1] + bhh[gc + 1];
            *reinterpret_cast<float2*>(&out[(size_t)m * G4H + gc]) = o;
        }
    }
}

// ================================================================================
// Persistent recurrent kernel: one layer, all 512 steps.
// 16 clusters (one per 16-batch group) x 8 CTAs (one per 32-hcol slice).
// h exchange = cp.async.bulk DSMEM pushes into peers' double-buffered Xs operand
// tiles + mbarrier full[s] (8 arrives, 16KB tx). NO cluster.sync in the loop.
// Block tile: 16 batch x 32 hcols (x4 gates), W_hh slice resident in SMEM.
// Warp w = gate w; thread computes 8 rows (4 f32x2 pairs) x 2 hcols.
// ================================================================================
template<bool STORE_SEQ>
__global__ __launch_bounds__(RTHREADS, 1) __cluster_dims__(CLSZ, 1, 1)
void lstm_persist(const float* __restrict__ Whh)
{
    extern __shared__ float sm[];
    float* Wt     = sm;                  // [256][130] k-major, gidx = g*32 + c
    float* Xs0    = Wt + 256 * 130;      // [256][16]  operand tile, stage 0
    float* Xs1    = Xs0 + 256 * 16;      // [256][16]  operand tile, stage 1
    float* Gs     = Xs1 + 256 * 16;      // [128][20]  gate exchange
    float* hstage = Gs + 128 * 20;       // [32][16]   outgoing h slice (2KB)

    const uint32_t smbase   = smem_u32(sm);
    const uint32_t XS_OFF0  = 256 * 130 * 4;
    const uint32_t XS_OFF1  = XS_OFF0 + 256 * 16 * 4;
    const uint32_t HST_OFF  = XS_OFF1 + 256 * 16 * 4 + 128 * 20 * 4;
    const uint32_t MBAR_OFF = HST_OFF + 32 * 16 * 4;

    const int tid  = threadIdx.x;
    const int gw   = tid >> 5;           // warp = gate 0..3
    const int lane = tid & 31;
    const int c2   = lane & 15;          // hcol pair: cols 2c2, 2c2+1
    const int rh   = lane >> 4;          // row half: rows 8rh..8rh+7
    const int cb   = blockIdx.x & 7;     // hcol slice = cluster rank 0..7
    const int bi   = blockIdx.x >> 3;    // batch group 0..15
    const int jb   = cb * 32;
    const int bb   = bi * 16;

    // ---- one-time: load W_hh slice transposed into SMEM (128 gidx x 256 k) ----
#pragma unroll 4
    for (int it = 0; it < 64; it++) {
        int idx = it * RTHREADS + tid;       // 8192 float4 chunks
        int r   = idx >> 6;                  // gidx 0..127 (g*32 + c)
        int k4  = (idx & 63) << 2;
        int gcol = (r >> 5) * HH + jb + (r & 31);
        float4 v = *reinterpret_cast<const float4*>(Whh + (size_t)gcol * HH + k4);
        Wt[(k4 + 0) * 130 + r] = v.x;
        Wt[(k4 + 1) * 130 + r] = v.y;
        Wt[(k4 + 2) * 130 + r] = v.z;
        Wt[(k4 + 3) * 130 + r] = v.w;
    }
    // ---- zero Xs0 (h(-1) = 0); Xs1 is filled by peers at end of step 0 ----
#pragma unroll
    for (int q = 0; q < 8; q++)
        *reinterpret_cast<float4*>(&Xs0[(q * RTHREADS + tid) * 4]) =
            make_float4(0.f, 0.f, 0.f, 0.f);

    // ---- mbarrier init, then one cluster barrier (inits visible to peers) ----
    if (tid == 0) {
        mbar_init(smbase + MBAR_OFF + 0, CLSZ);  // full[0]
        mbar_init(smbase + MBAR_OFF + 8, CLSZ);  // full[1]
    }
    __syncthreads();
    cluster_barrier();

    // epilogue item owned by this thread: hcol j (0..31), batch quad bq (0..3)
    const int j  = tid & 31;
    const int bq = tid >> 5;
    float creg[4] = {0.f, 0.f, 0.f, 0.f};
    int ph0 = 0, ph1 = 0;

    // prefetch xproj tile for t=0
    float xq[4][4];
    {
        const float* xb = g_xproj + ((size_t)0 * BB + bb + 4 * bq) * G4H + jb + j;
#pragma unroll
        for (int g = 0; g < 4; g++)
#pragma unroll
            for (int b = 0; b < 4; b++)
                xq[g][b] = __ldcg(xb + (size_t)b * G4H + g * HH);
    }

    for (int t = 0; t < TT; t++) {
        const int s = t & 1;
        // ---- wait for peers' h(t-1) (16KB tx + 8 arrives); t=0 uses zeros ----
        if (t > 0) {
            if (s) { mbar_wait(smbase + MBAR_OFF + 8, ph1); ph1 ^= 1; }
            else   { mbar_wait(smbase + MBAR_OFF + 0, ph0); ph0 ^= 1; }
        }
        const float* __restrict__ Xs = s ? Xs1 : Xs0;

        // ---- inner GEMM: gate gw, 8 rows (4 pairs) x 2 hcols per thread ----
        ull acc[4][2];
#pragma unroll
        for (int p = 0; p < 4; p++) { acc[p][0] = 0ull; acc[p][1] = 0ull; }

#pragma unroll 8
        for (int k = 0; k < HH; k++) {
            const float* xr = &Xs[k * 16 + 8 * rh];
            ull A0 = *reinterpret_cast<const ull*>(xr + 0);
            ull A1 = *reinterpret_cast<const ull*>(xr + 2);
            ull A2 = *reinterpret_cast<const ull*>(xr + 4);
            ull A3 = *reinterpret_cast<const ull*>(xr + 6);
            float2 wv = *reinterpret_cast<const float2*>(
                &Wt[k * 130 + gw * 32 + 2 * c2]);
            ull W0 = pack2(wv.x, wv.x);
            ull W1 = pack2(wv.y, wv.y);
            fma2(acc[0][0], A0, W0); fma2(acc[0][1], A0, W1);
            fma2(acc[1][0], A1, W0); fma2(acc[1][1], A1, W1);
            fma2(acc[2][0], A2, W0); fma2(acc[2][1], A2, W1);
            fma2(acc[3][0], A3, W0); fma2(acc[3][1], A3, W1);
        }

        // ---- gate exchange through SMEM: Gs[g*32 + col][b] ----
#pragma unroll
        for (int p = 0; p < 4; p++) {
            *reinterpret_cast<ull*>(
                &Gs[(gw * 32 + 2 * c2    ) * 20 + 8 * rh + 2 * p]) = acc[p][0];
            *reinterpret_cast<ull*>(
                &Gs[(gw * 32 + 2 * c2 + 1) * 20 + 8 * rh + 2 * p]) = acc[p][1];
        }
        __syncthreads();

        // ---- epilogue: thread owns (hcol j, batch quad bq) ----
        float4 vi = *reinterpret_cast<const float4*>(&Gs[(0 * 32 + j) * 20 + 4 * bq]);
        float4 vf = *reinterpret_cast<const float4*>(&Gs[(1 * 32 + j) * 20 + 4 * bq]);
        float4 vg = *reinterpret_cast<const float4*>(&Gs[(2 * 32 + j) * 20 + 4 * bq]);
        float4 vo = *reinterpret_cast<const float4*>(&Gs[(3 * 32 + j) * 20 + 4 * bq]);

        float gs[4][4];
        gs[0][0] = vi.x + xq[0][0]; gs[0][1] = vi.y + xq[0][1];
        gs[0][2] = vi.z + xq[0][2]; gs[0][3] = vi.w + xq[0][3];
        gs[1][0] = vf.x + xq[1][0]; gs[1][1] = vf.y + xq[1][1];
        gs[1][2] = vf.z + xq[1][2]; gs[1][3] = vf.w + xq[1][3];
        gs[2][0] = vg.x + xq[2][0]; gs[2][1] = vg.y + xq[2][1];
        gs[2][2] = vg.z + xq[2][2]; gs[2][3] = vg.w + xq[2][3];
        gs[3][0] = vo.x + xq[3][0]; gs[3][1] = vo.y + xq[3][1];
        gs[3][2] = vo.z + xq[3][2]; gs[3][3] = vo.w + xq[3][3];

        // prefetch next step's xproj tile (overlaps MUFU chain + transfer)
        if (t + 1 < TT) {
            const float* xb = g_xproj + ((size_t)(t + 1) * BB + bb + 4 * bq) * G4H
                            + jb + j;
#pragma unroll
            for (int g = 0; g < 4; g++)
#pragma unroll
                for (int b = 0; b < 4; b++)
                    xq[g][b] = __ldcg(xb + (size_t)b * G4H + g * HH);
        }

        float hv[4];
#pragma unroll
        for (int b = 0; b < 4; b++) {
            float iv = sigf(gs[0][b]);
            float fv = sigf(gs[1][b]);
            float gv = tanf_fast(gs[2][b]);
            float ov = sigf(gs[3][b]);
            float c  = fv * creg[b] + iv * gv;
            creg[b]  = c;
            hv[b]    = ov * tanf_fast(c);
        }
        float4 hq = make_float4(hv[0], hv[1], hv[2], hv[3]);

        // stage outgoing h slice [32 j][16 b] (2KB, contiguous [k][b] layout)
        *reinterpret_cast<float4*>(&hstage[j * 16 + 4 * bq]) = hq;

        size_t hoff = (size_t)(jb + j) * BB + bb + 4 * bq;
        if (STORE_SEQ)
            __stcg(reinterpret_cast<float4*>(
                g_h0T + (size_t)t * (HH * BB) + hoff), hq);
        if (t == TT - 1)
            __stcg(reinterpret_cast<float4*>(g_hlast + hoff), hq);

        __syncthreads();   // hstage complete; also guards Gs reuse next iter

        // ---- push h(t) slice into all 8 peers' Xs[s^1] + arrive on their bars ----
        if (t + 1 < TT && tid < CLSZ) {
            asm volatile("fence.proxy.async.shared::cta;" ::: "memory");
            uint32_t peer    = (uint32_t)tid;
            uint32_t loc_bar = smbase + MBAR_OFF + 8u * (uint32_t)(s ^ 1);
            uint32_t loc_dst = smbase + (s ? XS_OFF0 : XS_OFF1) + (uint32_t)cb * 2048u;
            uint32_t rem_bar = mapa_u32(loc_bar, peer);
            uint32_t rem_dst = mapa_u32(loc_dst, peer);
            send_slice(rem_dst, smbase + HST_OFF, rem_bar, 2048u);
        }
    }

    // no CTA may exit while peers might still touch its SMEM
    cluster_barrier();
}

// out[b] = h_last[b] . fc_w + fc_b; g_hlast is [H][B].
__global__ void fc_kernel(const float* __restrict__ w,
                          const float* __restrict__ bias,
                          float* __restrict__ out)
{
    int b = threadIdx.x;   // 256 threads, 1 block
    float s = 0.f;
#pragma unroll 8
    for (int j = 0; j < HH; j++)
        s += g_hlast[(size_t)j * BB + b] * w[j];
    out[b] = s + bias[0];
}

extern "C" void kernel_launch(void* const* d_in, const int* in_sizes, int n_in,
                              void* d_out, int out_size)
{
    const float* x     = (const float*)d_in[0];
    const float* W_ih0 = (const float*)d_in[1];
    const float* W_hh0 = (const float*)d_in[2];
    const float* b_ih0 = (const float*)d_in[3];
    const float* b_hh0 = (const float*)d_in[4];
    const float* W_ih1 = (const float*)d_in[5];
    const float* W_hh1 = (const float*)d_in[6];
    const float* b_ih1 = (const float*)d_in[7];
    const float* b_hh1 = (const float*)d_in[8];
    const float* fc_w  = (const float*)d_in[9];
    const float* fc_b  = (const float*)d_in[10];
    float* out = (float*)d_out;
    (void)in_sizes; (void)n_in; (void)out_size;

    // Wt + 2*Xs + Gs + hstage + 2 mbarriers
    const int rsmem = (256 * 130 + 2 * 256 * 16 + 128 * 20 + 32 * 16) * 4 + 16; // 178,192 B
    static bool attr_done = false;
    if (!attr_done) {
        cudaFuncSetAttribute(lstm_persist<true>,
                             cudaFuncAttributeMaxDynamicSharedMemorySize, rsmem);
        cudaFuncSetAttribute(lstm_persist<false>,
                             cudaFuncAttributeMaxDynamicSharedMemorySize, rsmem);
        attr_done = true;
    }

    float* xproj_ptr = nullptr;
    cudaGetSymbolAddress((void**)&xproj_ptr, g_xproj);
    float* h0T_ptr = nullptr;
    cudaGetSymbolAddress((void**)&h0T_ptr, g_h0T);

    dim3 ggrid(TT * BB / 64, G4H / 128);  // (2048, 8)

    // layer 0: input projection (time-parallel), then recurrence
    xproj_gemm<DD, 0><<<ggrid, 256>>>(x, W_ih0, b_ih0, b_hh0, xproj_ptr);
    lstm_persist<true><<<NBLK, RTHREADS, rsmem>>>(W_hh0);

    // layer 1: input projection from transposed layer-0 sequence, then recurrence
    xproj_gemm<HH, 1><<<ggrid, 256>>>(h0T_ptr, W_ih1, b_ih1, b_hh1, xproj_ptr);
    lstm_persist<false><<<NBLK, RTHREADS, rsmem>>>(W_hh1);

    fc_kernel<<<1, BB>>>(fc_w, fc_b, out);
}

// round 13
// speedup vs baseline: 1.6261x; 1.6261x over previous
#include <cuda_runtime.h>
#include <math.h>

// Problem constants
#define BB 256   // batch
#define TT 512   // time steps
#define DD 64    // input dim (layer 0)
#define HH 256   // hidden dim
#define G4H 1024 // 4*H

#define NBLK 128     // persistent grid size (16 groups x 8 CTAs), 1 block/SM
#define RTHREADS 128 // threads per persistent block (R8 proven tiling)
#define GRPSZ 8      // blocks per sync group (one batch slice)

typedef unsigned long long ull;

// ---------------- scratch (__device__ globals; no allocations allowed) ----------
__device__ float    g_xproj[(size_t)TT * BB * G4H]; // 512 MB: x @ W_ih^T + bias, [T][B][4H]
__device__ float    g_h0T[(size_t)TT * HH * BB];    // 128 MB: layer-0 outputs TRANSPOSED [T][H][B]
__device__ float    g_hT[2][HH * BB];               // ping-pong h state, TRANSPOSED [H][B]
__device__ unsigned g_ctr[2][16 * 64];              // per-group counters, 256B apart

// ---------------- packed fp32x2 helpers (Blackwell FFMA2 via PTX) ---------------
__device__ __forceinline__ ull pack2(float lo, float hi) {
    ull r;
    asm("mov.b64 %0, {%1, %2};" : "=l"(r) : "f"(lo), "f"(hi));
    return r;
}
__device__ __forceinline__ void unpack2(ull v, float& lo, float& hi) {
    asm("mov.b64 {%0, %1}, %2;" : "=f"(lo), "=f"(hi) : "l"(v));
}
__device__ __forceinline__ void fma2(ull& d, ull a, ull b) {
    asm("fma.rn.f32x2 %0, %1, %2, %0;" : "+l"(d) : "l"(a), "l"(b));
}

// ---------------- fast activations (MUFU-based, ~1e-6 rel err) ------------------
__device__ __forceinline__ float sigf(float x) {
    return __fdividef(1.0f, 1.0f + __expf(-x));
}
__device__ __forceinline__ float tanf_fast(float x) {
    return __fdividef(2.0f, 1.0f + __expf(-2.0f * x)) - 1.0f;
}

// ---------------- group barrier primitives ---------------------------------------
__device__ __forceinline__ void bar_red(unsigned* ctr) {
    asm volatile("red.release.gpu.add.u32 [%0], 1;" :: "l"(ctr) : "memory");
}
__device__ __forceinline__ unsigned ld_acq(const unsigned* p) {
    unsigned v;
    asm volatile("ld.acquire.gpu.u32 %0, [%1];" : "=r"(v) : "l"(p) : "memory");
    return v;
}

// ================================================================================
// Input-projection GEMM (best-measured R8/R9 version):
// out[m][gc] = sum_k A[m][k] * W[gc][k] + b_ih[gc] + b_hh[gc], m = t*BB + b.
// AMODE 0: A = x [B][T][D].  AMODE 1: A = g_h0T [T][H][B] (transposed).
// ================================================================================
template<int K, int AMODE>
__global__ __launch_bounds__(256)
void xproj_gemm(const float* __restrict__ A,
                const float* __restrict__ W,
                const float* __restrict__ bih,
                const float* __restrict__ bhh,
                float* __restrict__ out)
{
    __shared__ float At[32 * 68];    // [k][row], padded
    __shared__ float Wt[32 * 130];   // [k][col], even pad (8B-aligned rows)

    const int tid = threadIdx.x;
    const int tx  = tid & 15;        // col-pair lane: cols 2tx + 32j
    const int ty  = tid >> 4;        // rows ty + 16r
    const int m0  = blockIdx.x * 64;
    const int n0  = blockIdx.y * 128;

    ull acc[4][4];
#pragma unroll
    for (int r = 0; r < 4; r++)
#pragma unroll
        for (int j = 0; j < 4; j++) acc[r][j] = 0ull;

    for (int ks = 0; ks < K; ks += 32) {
        if (AMODE == 0) {
#pragma unroll
            for (int q = 0; q < 2; q++) {
                int chunk = tid + 256 * q;          // 512 float4 chunks
                int row   = chunk >> 3;
                int kq    = (chunk & 7) << 2;
                int m     = m0 + row;
                const float* ap = A + (size_t)(m & 255) * (TT * DD)
                                    + (size_t)(m >> 8) * DD + ks + kq;
                float4 v = *reinterpret_cast<const float4*>(ap);
                At[(kq + 0) * 68 + row] = v.x;
                At[(kq + 1) * 68 + row] = v.y;
                At[(kq + 2) * 68 + row] = v.z;
                At[(kq + 3) * 68 + row] = v.w;
            }
        } else {
            int t  = m0 >> 8;
            int b0 = m0 & 255;
#pragma unroll
            for (int q = 0; q < 2; q++) {
                int chunk = tid + 256 * q;          // 512 float4 chunks
                int k  = chunk >> 4;                // 0..31
                int b4 = (chunk & 15) << 2;
                float4 v = *reinterpret_cast<const float4*>(
                    A + ((size_t)t * HH + ks + k) * BB + b0 + b4);
                *reinterpret_cast<float4*>(&At[k * 68 + b4]) = v;
            }
        }
#pragma unroll
        for (int q = 0; q < 4; q++) {
            int chunk = tid + 256 * q;              // 1024 float4 chunks
            int col   = chunk >> 3;
            int kq    = (chunk & 7) << 2;
            float4 v  = *reinterpret_cast<const float4*>(
                W + (size_t)(n0 + col) * K + ks + kq);
            Wt[(kq + 0) * 130 + col] = v.x;
            Wt[(kq + 1) * 130 + col] = v.y;
            Wt[(kq + 2) * 130 + col] = v.z;
            Wt[(kq + 3) * 130 + col] = v.w;
        }
        __syncthreads();

#pragma unroll 8
        for (int k = 0; k < 32; k++) {
            ull w[4];
#pragma unroll
            for (int j = 0; j < 4; j++)
                w[j] = *reinterpret_cast<const ull*>(
                    &Wt[k * 130 + 2 * tx + 32 * j]);
#pragma unroll
            for (int r = 0; r < 4; r++) {
                float a = At[k * 68 + ty + 16 * r];
                ull aa = pack2(a, a);
#pragma unroll
                for (int j = 0; j < 4; j++) fma2(acc[r][j], aa, w[j]);
            }
        }
        __syncthreads();
    }

#pragma unroll
    for (int r = 0; r < 4; r++) {
        int m = m0 + ty + 16 * r;
#pragma unroll
        for (int j = 0; j < 4; j++) {
            int gc = n0 + 2 * tx + 32 * j;
            float lo, hi;
            unpack2(acc[r][j], lo, hi);
            float2 o;
            o.x = lo + bih[gc]     + bhh[gc];
            o.y = hi + bih[gc + 1] + bhh[gc + 1];
            *reinterpret_cast<float2*>(&out[(size_t)m * G4H + gc]) = o;
        }
    }
}

// ================================================================================
// Persistent recurrent kernel (R8 architecture, group-local sync):
// 16 independent GROUPS (one per 16-batch slice) x 8 CTAs (one per 32-hcol slice).
// Sync = per-group L2 counter (red.release by tid0 / tid0 ld.acquire poll +
// syncthreads broadcast). Groups drift independently — no chip-wide straggler max.
// Block tile: 16 batch x 32 hcols (x4 gates), W_hh slice resident in SMEM.
// Warp w = gate w; thread computes 8 rows (4 f32x2 pairs) x 2 hcols.
// h state exchanged TRANSPOSED [H][B] via L2 (__stcg/__ldcg), ping-pong buffered.
// ================================================================================
template<bool STORE_SEQ>
__global__ __launch_bounds__(RTHREADS, 1)
void lstm_persist(const float* __restrict__ Whh, int layer)
{
    extern __shared__ float sm[];
    float* Wt = sm;                      // [256][130]  k-major, gidx = g*32 + c
    float* Xs = Wt + 256 * 130;          // [256][20]   k-major h_prev tile [k][b]
    float* Gs = Xs + 256 * 20;           // [4*32][20]  gate exchange [gatecol][b]

    const int tid = threadIdx.x;
    const int gw  = tid >> 5;            // warp = gate 0..3
    const int lane = tid & 31;
    const int c2  = lane & 15;           // hcol pair: cols 2c2, 2c2+1
    const int rh  = lane >> 4;           // row half: rows 8rh..8rh+7
    const int cb  = blockIdx.x & 7;      // hcol slice 0..7
    const int bi  = blockIdx.x >> 3;     // batch group 0..15
    const int jb  = cb * 32;
    const int bb  = bi * 16;

    unsigned* ctr = &g_ctr[layer][bi * 64];
    unsigned  target = GRPSZ;

    // ---- one-time: load W_hh slice transposed into SMEM (128 gidx x 256 k) ----
#pragma unroll 4
    for (int it = 0; it < 64; it++) {
        int idx = it * RTHREADS + tid;       // 8192 float4 chunks
        int r   = idx >> 6;                  // gidx 0..127 (g*32 + c)
        int k4  = (idx & 63) << 2;
        int gcol = (r >> 5) * HH + jb + (r & 31);
        float4 v = *reinterpret_cast<const float4*>(Whh + (size_t)gcol * HH + k4);
        Wt[(k4 + 0) * 130 + r] = v.x;
        Wt[(k4 + 1) * 130 + r] = v.y;
        Wt[(k4 + 2) * 130 + r] = v.z;
        Wt[(k4 + 3) * 130 + r] = v.w;
    }
    // ---- zero this CTA's slice of h(-1): hcols jb..jb+31, batch bb..bb+15 ----
    {
        int r  = tid >> 2;                   // 0..31 (hcol within slice)
        int c4 = (tid & 3) << 2;             // 0,4,8,12
        float4 z = make_float4(0.f, 0.f, 0.f, 0.f);
        __stcg(reinterpret_cast<float4*>(
            &g_hT[0][(size_t)(jb + r) * BB + bb + c4]), z);
    }
    __syncthreads();
    if (tid == 0) { __threadfence(); bar_red(ctr); }

    // epilogue item owned by this thread: hcol j (0..31), batch quad bq (0..3)
    const int j  = tid & 31;
    const int bq = tid >> 5;
    float creg[4] = {0.f, 0.f, 0.f, 0.f};

    // prefetch xproj tile for t=0
    float xq[4][4];
    {
        const float* xb = g_xproj + ((size_t)0 * BB + bb + 4 * bq) * G4H + jb + j;
#pragma unroll
        for (int g = 0; g < 4; g++)
#pragma unroll
            for (int b = 0; b < 4; b++)
                xq[g][b] = __ldcg(xb + (size_t)b * G4H + g * HH);
    }

    for (int t = 0; t < TT; t++) {
        // ---- wait: our 8-block group published h(t-1) ----
        if (tid == 0) {
            while (ld_acq(ctr) < target) {}
        }
        __syncthreads();
        target += GRPSZ;

        const float* __restrict__ hprev = g_hT[t & 1];
        float* __restrict__ hnext = g_hT[(t & 1) ^ 1];

        // ---- stage h_prev tile [256 k][16 b] into Xs (pure float4, L2 reads) ----
#pragma unroll
        for (int q = 0; q < 8; q++) {
            int chunk = q * RTHREADS + tid;      // 1024 chunks
            int k  = chunk >> 2;
            int c4 = (chunk & 3) << 2;
            float4 v = __ldcg(reinterpret_cast<const float4*>(
                hprev + (size_t)k * BB + bb + c4));
            *reinterpret_cast<float4*>(&Xs[k * 20 + c4]) = v;
        }
        __syncthreads();

        // ---- inner GEMM: gate gw, 8 rows (4 pairs) x 2 hcols per thread ----
        ull acc[4][2];
#pragma unroll
        for (int p = 0; p < 4; p++) { acc[p][0] = 0ull; acc[p][1] = 0ull; }

#pragma unroll 8
        for (int k = 0; k < HH; k++) {
            const float* xr = &Xs[k * 20 + 8 * rh];
            ull A0 = *reinterpret_cast<const ull*>(xr + 0);
            ull A1 = *reinterpret_cast<const ull*>(xr + 2);
            ull A2 = *reinterpret_cast<const ull*>(xr + 4);
            ull A3 = *reinterpret_cast<const ull*>(xr + 6);
            float2 wv = *reinterpret_cast<const float2*>(
                &Wt[k * 130 + gw * 32 + 2 * c2]);
            ull W0 = pack2(wv.x, wv.x);
            ull W1 = pack2(wv.y, wv.y);
            fma2(acc[0][0], A0, W0); fma2(acc[0][1], A0, W1);
            fma2(acc[1][0], A1, W0); fma2(acc[1][1], A1, W1);
            fma2(acc[2][0], A2, W0); fma2(acc[2][1], A2, W1);
            fma2(acc[3][0], A3, W0); fma2(acc[3][1], A3, W1);
        }

        // ---- gate exchange through SMEM: Gs[g*32 + col][b] ----
#pragma unroll
        for (int p = 0; p < 4; p++) {
            *reinterpret_cast<ull*>(
                &Gs[(gw * 32 + 2 * c2    ) * 20 + 8 * rh + 2 * p]) = acc[p][0];
            *reinterpret_cast<ull*>(
                &Gs[(gw * 32 + 2 * c2 + 1) * 20 + 8 * rh + 2 * p]) = acc[p][1];
        }
        __syncthreads();

        // ---- epilogue: thread owns (hcol j, batch quad bq) ----
        float4 vi = *reinterpret_cast<const float4*>(&Gs[(0 * 32 + j) * 20 + 4 * bq]);
        float4 vf = *reinterpret_cast<const float4*>(&Gs[(1 * 32 + j) * 20 + 4 * bq]);
        float4 vg = *reinterpret_cast<const float4*>(&Gs[(2 * 32 + j) * 20 + 4 * bq]);
        float4 vo = *reinterpret_cast<const float4*>(&Gs[(3 * 32 + j) * 20 + 4 * bq]);

        float gs[4][4];
        gs[0][0] = vi.x + xq[0][0]; gs[0][1] = vi.y + xq[0][1];
        gs[0][2] = vi.z + xq[0][2]; gs[0][3] = vi.w + xq[0][3];
        gs[1][0] = vf.x + xq[1][0]; gs[1][1] = vf.y + xq[1][1];
        gs[1][2] = vf.z + xq[1][2]; gs[1][3] = vf.w + xq[1][3];
        gs[2][0] = vg.x + xq[2][0]; gs[2][1] = vg.y + xq[2][1];
        gs[2][2] = vg.z + xq[2][2]; gs[2][3] = vg.w + xq[2][3];
        gs[3][0] = vo.x + xq[3][0]; gs[3][1] = vo.y + xq[3][1];
        gs[3][2] = vo.z + xq[3][2]; gs[3][3] = vo.w + xq[3][3];

        // prefetch next step's xproj tile (overlaps MUFU chain + barrier)
        if (t + 1 < TT) {
            const float* xb = g_xproj + ((size_t)(t + 1) * BB + bb + 4 * bq) * G4H
                            + jb + j;
#pragma unroll
            for (int g = 0; g < 4; g++)
#pragma unroll
                for (int b = 0; b < 4; b++)
                    xq[g][b] = __ldcg(xb + (size_t)b * G4H + g * HH);
        }

        float hv[4];
#pragma unroll
        for (int b = 0; b < 4; b++) {
            float iv = sigf(gs[0][b]);
            float fv = sigf(gs[1][b]);
            float gv = tanf_fast(gs[2][b]);
            float ov = sigf(gs[3][b]);
            float c  = fv * creg[b] + iv * gv;
            creg[b]  = c;
            hv[b]    = ov * tanf_fast(c);
        }

        float4 hq = make_float4(hv[0], hv[1], hv[2], hv[3]);
        size_t hoff = (size_t)(jb + j) * BB + bb + 4 * bq;
        __stcg(reinterpret_cast<float4*>(hnext + hoff), hq);
        if (STORE_SEQ)
            __stcg(reinterpret_cast<float4*>(
                g_h0T + (size_t)t * (HH * BB) + hoff), hq);

        // ---- arrive: publish h(t) to the group ----
        __syncthreads();   // all threads' stcg issued; also guards Xs/Gs reuse
        if (tid == 0) { __threadfence(); bar_red(ctr); }
    }
}

// zero barrier counters (run once per replay, before everything)
__global__ void init_kernel()
{
    int i = threadIdx.x;
    for (; i < 2 * 16 * 64; i += blockDim.x)
        (&g_ctr[0][0])[i] = 0u;
}

// out[b] = h_last[b] . fc_w + fc_b. TT even -> final h of layer 1 is g_hT[0] ([H][B]).
__global__ void fc_kernel(const float* __restrict__ w,
                          const float* __restrict__ bias,
                          float* __restrict__ out)
{
    int b = threadIdx.x;   // 256 threads, 1 block
    float s = 0.f;
#pragma unroll 8
    for (int j = 0; j < HH; j++)
        s += g_hT[0][(size_t)j * BB + b] * w[j];
    out[b] = s + bias[0];
}

extern "C" void kernel_launch(void* const* d_in, const int* in_sizes, int n_in,
                              void* d_out, int out_size)
{
    const float* x     = (const float*)d_in[0];
    const float* W_ih0 = (const float*)d_in[1];
    const float* W_hh0 = (const float*)d_in[2];
    const float* b_ih0 = (const float*)d_in[3];
    const float* b_hh0 = (const float*)d_in[4];
    const float* W_ih1 = (const float*)d_in[5];
    const float* W_hh1 = (const float*)d_in[6];
    const float* b_ih1 = (const float*)d_in[7];
    const float* b_hh1 = (const float*)d_in[8];
    const float* fc_w  = (const float*)d_in[9];
    const float* fc_b  = (const float*)d_in[10];
    float* out = (float*)d_out;
    (void)in_sizes; (void)n_in; (void)out_size;

    const int rsmem = (256 * 130 + 256 * 20 + 4 * 32 * 20) * sizeof(float); // 163,840 B
    static bool attr_done = false;
    if (!attr_done) {
        cudaFuncSetAttribute(lstm_persist<true>,
                             cudaFuncAttributeMaxDynamicSharedMemorySize, rsmem);
        cudaFuncSetAttribute(lstm_persist<false>,
                             cudaFuncAttributeMaxDynamicSharedMemorySize, rsmem);
        attr_done = true;
    }

    float* xproj_ptr = nullptr;
    cudaGetSymbolAddress((void**)&xproj_ptr, g_xproj);
    float* h0T_ptr = nullptr;
    cudaGetSymbolAddress((void**)&h0T_ptr, g_h0T);

    init_kernel<<<1, 256>>>();

    dim3 ggrid(TT * BB / 64, G4H / 128);  // (2048, 8)

    // layer 0: input projection (time-parallel), then recurrence
    xproj_gemm<DD, 0><<<ggrid, 256>>>(x, W_ih0, b_ih0, b_hh0, xproj_ptr);
    lstm_persist<true><<<NBLK, RTHREADS, rsmem>>>(W_hh0, 0);

    // layer 1: input projection from transposed layer-0 sequence, then recurrence
    xproj_gemm<HH, 1><<<ggrid, 256>>>(h0T_ptr, W_ih1, b_ih1, b_hh1, xproj_ptr);
    lstm_persist<false><<<NBLK, RTHREADS, rsmem>>>(W_hh1, 1);

    fc_kernel<<<1, BB>>>(fc_w, fc_b, out);
}

// round 14
// speedup vs baseline: 1.6589x; 1.0202x over previous
#include <cuda_runtime.h>
#include <math.h>

// Problem constants
#define BB 256   // batch
#define TT 512   // time steps
#define DD 64    // input dim (layer 0)
#define HH 256   // hidden dim
#define G4H 1024 // 4*H

#define NBLK 128     // persistent grid size (16 groups x 8 CTAs), 1 block/SM
#define RTHREADS 256 // persistent block: 8 warps = 4 gates x 2 K-halves
#define GRPSZ 8      // blocks per sync group (one batch slice)

typedef unsigned long long ull;

// ---------------- scratch (__device__ globals; no allocations allowed) ----------
__device__ float    g_xproj[(size_t)TT * BB * G4H]; // 512 MB: x @ W_ih^T + bias, [T][B][4H]
__device__ float    g_h0T[(size_t)TT * HH * BB];    // 128 MB: layer-0 outputs TRANSPOSED [T][H][B]
__device__ float    g_hT[2][HH * BB];               // ping-pong h state, TRANSPOSED [H][B]
__device__ unsigned g_ctr[2][16 * 64];              // per-group counters, 256B apart

// ---------------- packed fp32x2 helpers (Blackwell FFMA2 via PTX) ---------------
__device__ __forceinline__ ull pack2(float lo, float hi) {
    ull r;
    asm("mov.b64 %0, {%1, %2};" : "=l"(r) : "f"(lo), "f"(hi));
    return r;
}
__device__ __forceinline__ void unpack2(ull v, float& lo, float& hi) {
    asm("mov.b64 {%0, %1}, %2;" : "=f"(lo), "=f"(hi) : "l"(v));
}
__device__ __forceinline__ void fma2(ull& d, ull a, ull b) {
    asm("fma.rn.f32x2 %0, %1, %2, %0;" : "+l"(d) : "l"(a), "l"(b));
}

// ---------------- fast activations (MUFU-based, ~1e-6 rel err) ------------------
__device__ __forceinline__ float sigf(float x) {
    return __fdividef(1.0f, 1.0f + __expf(-x));
}
__device__ __forceinline__ float tanf_fast(float x) {
    return __fdividef(2.0f, 1.0f + __expf(-2.0f * x)) - 1.0f;
}

// ---------------- group barrier primitives ---------------------------------------
__device__ __forceinline__ void bar_red(unsigned* ctr) {
    asm volatile("red.release.gpu.add.u32 [%0], 1;" :: "l"(ctr) : "memory");
}
__device__ __forceinline__ unsigned ld_acq(const unsigned* p) {
    unsigned v;
    asm volatile("ld.acquire.gpu.u32 %0, [%1];" : "=r"(v) : "l"(p) : "memory");
    return v;
}

// ================================================================================
// Input-projection GEMM (best-measured R8/R9 version, unchanged):
// out[m][gc] = sum_k A[m][k] * W[gc][k] + b_ih[gc] + b_hh[gc], m = t*BB + b.
// AMODE 0: A = x [B][T][D].  AMODE 1: A = g_h0T [T][H][B] (transposed).
// ================================================================================
template<int K, int AMODE>
__global__ __launch_bounds__(256)
void xproj_gemm(const float* __restrict__ A,
                const float* __restrict__ W,
                const float* __restrict__ bih,
                const float* __restrict__ bhh,
                float* __restrict__ out)
{
    __shared__ float At[32 * 68];    // [k][row], padded
    __shared__ float Wt[32 * 130];   // [k][col], even pad (8B-aligned rows)

    const int tid = threadIdx.x;
    const int tx  = tid & 15;        // col-pair lane: cols 2tx + 32j
    const int ty  = tid >> 4;        // rows ty + 16r
    const int m0  = blockIdx.x * 64;
    const int n0  = blockIdx.y * 128;

    ull acc[4][4];
#pragma unroll
    for (int r = 0; r < 4; r++)
#pragma unroll
        for (int j = 0; j < 4; j++) acc[r][j] = 0ull;

    for (int ks = 0; ks < K; ks += 32) {
        if (AMODE == 0) {
#pragma unroll
            for (int q = 0; q < 2; q++) {
                int chunk = tid + 256 * q;          // 512 float4 chunks
                int row   = chunk >> 3;
                int kq    = (chunk & 7) << 2;
                int m     = m0 + row;
                const float* ap = A + (size_t)(m & 255) * (TT * DD)
                                    + (size_t)(m >> 8) * DD + ks + kq;
                float4 v = *reinterpret_cast<const float4*>(ap);
                At[(kq + 0) * 68 + row] = v.x;
                At[(kq + 1) * 68 + row] = v.y;
                At[(kq + 2) * 68 + row] = v.z;
                At[(kq + 3) * 68 + row] = v.w;
            }
        } else {
            int t  = m0 >> 8;
            int b0 = m0 & 255;
#pragma unroll
            for (int q = 0; q < 2; q++) {
                int chunk = tid + 256 * q;          // 512 float4 chunks
                int k  = chunk >> 4;                // 0..31
                int b4 = (chunk & 15) << 2;
                float4 v = *reinterpret_cast<const float4*>(
                    A + ((size_t)t * HH + ks + k) * BB + b0 + b4);
                *reinterpret_cast<float4*>(&At[k * 68 + b4]) = v;
            }
        }
#pragma unroll
        for (int q = 0; q < 4; q++) {
            int chunk = tid + 256 * q;              // 1024 float4 chunks
            int col   = chunk >> 3;
            int kq    = (chunk & 7) << 2;
            float4 v  = *reinterpret_cast<const float4*>(
                W + (size_t)(n0 + col) * K + ks + kq);
            Wt[(kq + 0) * 130 + col] = v.x;
            Wt[(kq + 1) * 130 + col] = v.y;
            Wt[(kq + 2) * 130 + col] = v.z;
            Wt[(kq + 3) * 130 + col] = v.w;
        }
        __syncthreads();

#pragma unroll 8
        for (int k = 0; k < 32; k++) {
            ull w[4];
#pragma unroll
            for (int j = 0; j < 4; j++)
                w[j] = *reinterpret_cast<const ull*>(
                    &Wt[k * 130 + 2 * tx + 32 * j]);
#pragma unroll
            for (int r = 0; r < 4; r++) {
                float a = At[k * 68 + ty + 16 * r];
                ull aa = pack2(a, a);
#pragma unroll
                for (int j = 0; j < 4; j++) fma2(acc[r][j], aa, w[j]);
            }
        }
        __syncthreads();
    }

#pragma unroll
    for (int r = 0; r < 4; r++) {
        int m = m0 + ty + 16 * r;
#pragma unroll
        for (int j = 0; j < 4; j++) {
            int gc = n0 + 2 * tx + 32 * j;
            float lo, hi;
            unpack2(acc[r][j], lo, hi);
            float2 o;
            o.x = lo + bih[gc]     + bhh[gc];
            o.y = hi + bih[gc + 1] + bhh[gc + 1];
            *reinterpret_cast<float2*>(&out[(size_t)m * G4H + gc]) = o;
        }
    }
}

// ================================================================================
// Persistent recurrent kernel: 16 groups (16-batch slices) x 8 CTAs (32-hcol).
// Sync = per-group L2 counter (unchanged from R13 WIN).
// NEW: 256 threads = 8 warps = (4 gates) x (2 K-halves of 128). Each warp runs the
// proven FMA-bound inner loop (8 FFMA2 + 5 LDS per k) over its K-half; the two
// half-sums are combined in the epilogue via the existing Gs SMEM exchange.
// 2 warps/SMSP hide LDS/MUFU/L2 latency; FMA floor unchanged (~4.1k cyc/step).
// ================================================================================
template<bool STORE_SEQ>
__global__ __launch_bounds__(RTHREADS, 1)
void lstm_persist(const float* __restrict__ Whh, int layer)
{
    extern __shared__ float sm[];
    float* Wt = sm;                      // [256][130]  k-major, gidx = g*32 + c
    float* Xs = Wt + 256 * 130;          // [256][20]   k-major h_prev tile [k][b]
    float* Gs = Xs + 256 * 20;           // [2 khalf][128 gatecol][20]  half-sums

    const int tid  = threadIdx.x;
    const int wid  = tid >> 5;
    const int gw   = wid & 3;            // gate 0..3
    const int kh   = wid >> 2;           // K-half 0..1
    const int lane = tid & 31;
    const int c2   = lane & 15;          // hcol pair: cols 2c2, 2c2+1
    const int rh   = lane >> 4;          // row half: rows 8rh..8rh+7
    const int cb   = blockIdx.x & 7;     // hcol slice 0..7
    const int bi   = blockIdx.x >> 3;    // batch group 0..15
    const int jb   = cb * 32;
    const int bb   = bi * 16;
    const int kbase = kh * 128;

    unsigned* ctr = &g_ctr[layer][bi * 64];
    unsigned  target = GRPSZ;

    // ---- one-time: load W_hh slice transposed into SMEM (128 gidx x 256 k) ----
#pragma unroll 4
    for (int it = 0; it < 32; it++) {
        int idx = it * RTHREADS + tid;       // 8192 float4 chunks
        int r   = idx >> 6;                  // gidx 0..127 (g*32 + c)
        int k4  = (idx & 63) << 2;
        int gcol = (r >> 5) * HH + jb + (r & 31);
        float4 v = *reinterpret_cast<const float4*>(Whh + (size_t)gcol * HH + k4);
        Wt[(k4 + 0) * 130 + r] = v.x;
        Wt[(k4 + 1) * 130 + r] = v.y;
        Wt[(k4 + 2) * 130 + r] = v.z;
        Wt[(k4 + 3) * 130 + r] = v.w;
    }
    // ---- zero this CTA's slice of h(-1): hcols jb..jb+31, batch bb..bb+15 ----
    {
        int r   = tid >> 3;                  // 0..31 (hcol within slice)
        int c2i = (tid & 7) << 1;            // 0,2,...,14
        float2 z = make_float2(0.f, 0.f);
        __stcg(reinterpret_cast<float2*>(
            &g_hT[0][(size_t)(jb + r) * BB + bb + c2i]), z);
    }
    __syncthreads();
    if (tid == 0) { __threadfence(); bar_red(ctr); }

    // epilogue item owned by this thread: hcol j (0..31), batch pair bh (0..7)
    const int j  = tid & 31;
    const int bh = tid >> 5;
    float creg[2] = {0.f, 0.f};

    // prefetch xproj tile for t=0
    float xq[4][2];
    {
        const float* xb = g_xproj + ((size_t)0 * BB + bb + 2 * bh) * G4H + jb + j;
#pragma unroll
        for (int g = 0; g < 4; g++) {
            xq[g][0] = __ldcg(xb + g * HH);
            xq[g][1] = __ldcg(xb + G4H + g * HH);
        }
    }

    for (int t = 0; t < TT; t++) {
        // ---- wait: our 8-block group published h(t-1) ----
        if (tid == 0) {
            while (ld_acq(ctr) < target) {}
        }
        __syncthreads();
        target += GRPSZ;

        const float* __restrict__ hprev = g_hT[t & 1];
        float* __restrict__ hnext = g_hT[(t & 1) ^ 1];

        // ---- stage h_prev tile [256 k][16 b] into Xs (pure float4, L2 reads) ----
#pragma unroll
        for (int q = 0; q < 4; q++) {
            int chunk = q * RTHREADS + tid;      // 1024 chunks
            int k  = chunk >> 2;
            int c4 = (chunk & 3) << 2;
            float4 v = __ldcg(reinterpret_cast<const float4*>(
                hprev + (size_t)k * BB + bb + c4));
            *reinterpret_cast<float4*>(&Xs[k * 20 + c4]) = v;
        }
        __syncthreads();

        // ---- inner GEMM: gate gw, K-half kh; 8 rows (4 pairs) x 2 hcols ----
        ull acc[4][2];
#pragma unroll
        for (int p = 0; p < 4; p++) { acc[p][0] = 0ull; acc[p][1] = 0ull; }

        {
            const float* xk = &Xs[kbase * 20 + 8 * rh];
            const float* wk = &Wt[kbase * 130 + gw * 32 + 2 * c2];
#pragma unroll 8
            for (int k = 0; k < 128; k++) {
                const float* xr = xk + k * 20;
                ull A0 = *reinterpret_cast<const ull*>(xr + 0);
                ull A1 = *reinterpret_cast<const ull*>(xr + 2);
                ull A2 = *reinterpret_cast<const ull*>(xr + 4);
                ull A3 = *reinterpret_cast<const ull*>(xr + 6);
                float2 wv = *reinterpret_cast<const float2*>(wk + k * 130);
                ull W0 = pack2(wv.x, wv.x);
                ull W1 = pack2(wv.y, wv.y);
                fma2(acc[0][0], A0, W0); fma2(acc[0][1], A0, W1);
                fma2(acc[1][0], A1, W0); fma2(acc[1][1], A1, W1);
                fma2(acc[2][0], A2, W0); fma2(acc[2][1], A2, W1);
                fma2(acc[3][0], A3, W0); fma2(acc[3][1], A3, W1);
            }
        }

        // ---- half-sum exchange through SMEM: Gs[kh][g*32 + col][b] ----
        {
            float* gsh = Gs + kh * (128 * 20);
#pragma unroll
            for (int p = 0; p < 4; p++) {
                *reinterpret_cast<ull*>(
                    &gsh[(gw * 32 + 2 * c2    ) * 20 + 8 * rh + 2 * p]) = acc[p][0];
                *reinterpret_cast<ull*>(
                    &gsh[(gw * 32 + 2 * c2 + 1) * 20 + 8 * rh + 2 * p]) = acc[p][1];
            }
        }
        __syncthreads();

        // ---- epilogue: thread owns (hcol j, batch pair bh); sum the K-halves ----
        float gs[4][2];
#pragma unroll
        for (int g = 0; g < 4; g++) {
            float2 v0 = *reinterpret_cast<const float2*>(
                &Gs[(g * 32 + j) * 20 + 2 * bh]);
            float2 v1 = *reinterpret_cast<const float2*>(
                &Gs[128 * 20 + (g * 32 + j) * 20 + 2 * bh]);
            gs[g][0] = v0.x + v1.x + xq[g][0];
            gs[g][1] = v0.y + v1.y + xq[g][1];
        }

        // prefetch next step's xproj tile (overlaps MUFU chain + barrier)
        if (t + 1 < TT) {
            const float* xb = g_xproj + ((size_t)(t + 1) * BB + bb + 2 * bh) * G4H
                            + jb + j;
#pragma unroll
            for (int g = 0; g < 4; g++) {
                xq[g][0] = __ldcg(xb + g * HH);
                xq[g][1] = __ldcg(xb + G4H + g * HH);
            }
        }

        float hv[2];
#pragma unroll
        for (int b = 0; b < 2; b++) {
            float iv = sigf(gs[0][b]);
            float fv = sigf(gs[1][b]);
            float gv = tanf_fast(gs[2][b]);
            float ov = sigf(gs[3][b]);
            float c  = fv * creg[b] + iv * gv;
            creg[b]  = c;
            hv[b]    = ov * tanf_fast(c);
        }

        float2 hq = make_float2(hv[0], hv[1]);
        size_t hoff = (size_t)(jb + j) * BB + bb + 2 * bh;
        __stcg(reinterpret_cast<float2*>(hnext + hoff), hq);
        if (STORE_SEQ)
            __stcg(reinterpret_cast<float2*>(
                g_h0T + (size_t)t * (HH * BB) + hoff), hq);

        // ---- arrive: publish h(t) to the group ----
        __syncthreads();   // all threads' stcg issued; also guards Xs/Gs reuse
        if (tid == 0) { __threadfence(); bar_red(ctr); }
    }
}

// zero barrier counters (run once per replay, before everything)
__global__ void init_kernel()
{
    int i = threadIdx.x;
    for (; i < 2 * 16 * 64; i += blockDim.x)
        (&g_ctr[0][0])[i] = 0u;
}

// out[b] = h_last[b] . fc_w + fc_b. TT even -> final h of layer 1 is g_hT[0] ([H][B]).
__global__ void fc_kernel(const float* __restrict__ w,
                          const float* __restrict__ bias,
                          float* __restrict__ out)
{
    int b = threadIdx.x;   // 256 threads, 1 block
    float s = 0.f;
#pragma unroll 8
    for (int j = 0; j < HH; j++)
        s += g_hT[0][(size_t)j * BB + b] * w[j];
    out[b] = s + bias[0];
}

extern "C" void kernel_launch(void* const* d_in, const int* in_sizes, int n_in,
                              void* d_out, int out_size)
{
    const float* x     = (const float*)d_in[0];
    const float* W_ih0 = (const float*)d_in[1];
    const float* W_hh0 = (const float*)d_in[2];
    const float* b_ih0 = (const float*)d_in[3];
    const float* b_hh0 = (const float*)d_in[4];
    const float* W_ih1 = (const float*)d_in[5];
    const float* W_hh1 = (const float*)d_in[6];
    const float* b_ih1 = (const float*)d_in[7];
    const float* b_hh1 = (const float*)d_in[8];
    const float* fc_w  = (const float*)d_in[9];
    const float* fc_b  = (const float*)d_in[10];
    float* out = (float*)d_out;
    (void)in_sizes; (void)n_in; (void)out_size;

    // Wt + Xs + Gs(2 halves)
    const int rsmem = (256 * 130 + 256 * 20 + 2 * 128 * 20) * sizeof(float); // 174,080 B
    static bool attr_done = false;
    if (!attr_done) {
        cudaFuncSetAttribute(lstm_persist<true>,
                             cudaFuncAttributeMaxDynamicSharedMemorySize, rsmem);
        cudaFuncSetAttribute(lstm_persist<false>,
                             cudaFuncAttributeMaxDynamicSharedMemorySize, rsmem);
        attr_done = true;
    }

    float* xproj_ptr = nullptr;
    cudaGetSymbolAddress((void**)&xproj_ptr, g_xproj);
    float* h0T_ptr = nullptr;
    cudaGetSymbolAddress((void**)&h0T_ptr, g_h0T);

    init_kernel<<<1, 256>>>();

    dim3 ggrid(TT * BB / 64, G4H / 128);  // (2048, 8)

    // layer 0: input projection (time-parallel), then recurrence
    xproj_gemm<DD, 0><<<ggrid, 256>>>(x, W_ih0, b_ih0, b_hh0, xproj_ptr);
    lstm_persist<true><<<NBLK, RTHREADS, rsmem>>>(W_hh0, 0);

    // layer 1: input projection from transposed layer-0 sequence, then recurrence
    xproj_gemm<HH, 1><<<ggrid, 256>>>(h0T_ptr, W_ih1, b_ih1, b_hh1, xproj_ptr);
    lstm_persist<false><<<NBLK, RTHREADS, rsmem>>>(W_hh1, 1);

    fc_kernel<<<1, BB>>>(fc_w, fc_b, out);
}